// round 12
// baseline (speedup 1.0000x reference)
#include <cuda_runtime.h>
#include <float.h>

// Fused MaxPool(2x2,s1,SAME) -> depthwise 3x3 binomial blur -> AvgPool(2x2,s2)
// == separable 4x4 stencil w=(1,3,3,1)/8 stride 2 over maxpool output y.
//
// R11: the binding constraint is the LTS (L2) throughput cap (~6300 B/cyc
// measured ~= ncu 50%), not DRAM latency. Cut L2-side read amplification by
// widening strips to 4 output rows (11 x-rows per 8 consumed: 1.375x vs
// 1.75x). Pipeline shape is R3-verbatim: double-buffered column pairs,
// 22-load 256B bursts, predicated-select loads.

#define TILE_R 4                 // output rows per strip
#define NROWT  14                // 56 / TILE_R
#define NXROWS 11                // x rows per strip  (2*TILE_R + 3)
#define NY     10                // y rows per strip  (2*TILE_R + 2)
#define WCHUNK 14                // output cols per strip
#define NCH    4                 // 56 / WCHUNK
#define ROWSTR (112*64)          // float2 per x row
#define PXSTR  64                // float2 per pixel

__device__ __forceinline__ float2 f2max(float2 a, float2 b) {
    return make_float2(fmaxf(a.x,b.x), fmaxf(a.y,b.y));
}
__device__ __forceinline__ void f2fma(float2& a, float w, float2 v) {
    a.x = fmaf(w, v.x, a.x); a.y = fmaf(w, v.y, a.y);
}

// Load 11 x-rows of one column. Rows 1..8 always in range; row 0 invalid only
// for the top strip, rows 9,10 invalid only for the bottom strip.
#define LOADCOL(dst, c, cOk) do {                                         \
    const float2* _p = base + (long long)(c) * PXSTR;                     \
    dst[0]  = ((cOk) && okTop) ? __ldg(_p)               : NEG;           \
    dst[1]  = (cOk) ? __ldg(_p +  1*ROWSTR) : NEG;                        \
    dst[2]  = (cOk) ? __ldg(_p +  2*ROWSTR) : NEG;                        \
    dst[3]  = (cOk) ? __ldg(_p +  3*ROWSTR) : NEG;                        \
    dst[4]  = (cOk) ? __ldg(_p +  4*ROWSTR) : NEG;                        \
    dst[5]  = (cOk) ? __ldg(_p +  5*ROWSTR) : NEG;                        \
    dst[6]  = (cOk) ? __ldg(_p +  6*ROWSTR) : NEG;                        \
    dst[7]  = (cOk) ? __ldg(_p +  7*ROWSTR) : NEG;                        \
    dst[8]  = (cOk) ? __ldg(_p +  8*ROWSTR) : NEG;                        \
    dst[9]  = ((cOk) && okBot) ? __ldg(_p +  9*ROWSTR) : NEG;             \
    dst[10] = ((cOk) && okBot) ? __ldg(_p + 10*ROWSTR) : NEG;             \
} while (0)

// Column pair-maxes over x rows k,k+1.
#define MAKECM(cm, xv) do {                                               \
    _Pragma("unroll")                                                     \
    for (int _k = 0; _k < NY; _k++) cm[_k] = f2max(xv[_k], xv[_k+1]);     \
} while (0)

// Finalize one y column (TY literal after unroll): vertical (1,3,3,1)/8 per
// output row, then scatter into the two pending output-column accumulators.
#define STEP(prevcm, curcm, TY) do {                                      \
    const bool _skip = ((TY)==0 && leftSkip) || ((TY)==29 && rightSkip);  \
    if (!_skip) {                                                         \
        float2 yc[NY];                                                    \
        _Pragma("unroll")                                                 \
        for (int _k = 0; _k < NY; _k++)                                   \
            yc[_k] = f2max(prevcm[_k], curcm[_k]);                        \
        if (!okTop) yc[0]    = ZERO;                                      \
        if (!okBot) yc[NY-1] = ZERO;                                      \
        const int   _m  = (TY) >> 1;                                      \
        const float _wA = ((TY) & 1) ? wv1 : wv0;                         \
        const float _wB = ((TY) & 1) ? wv0 : wv1;                         \
        _Pragma("unroll")                                                 \
        for (int _rl = 0; _rl < TILE_R; _rl++) {                          \
            float2 V = ZERO;                                              \
            f2fma(V, wv0, yc[2*_rl + 0]);                                 \
            f2fma(V, wv1, yc[2*_rl + 1]);                                 \
            f2fma(V, wv1, yc[2*_rl + 2]);                                 \
            f2fma(V, wv0, yc[2*_rl + 3]);                                 \
            if (_m < WCHUNK) f2fma(acc[_rl][_m & 1], _wA, V);             \
            if (_m >= 1)     f2fma(acc[_rl][(_m & 1) ^ 1], _wB, V);       \
        }                                                                 \
    }                                                                     \
} while (0)

__global__ void __launch_bounds__(128, 3)
mbp_kernel(const float2* __restrict__ x, float2* __restrict__ out) {
    const int lane   = threadIdx.x;
    const int wid    = blockIdx.x * 4 + threadIdx.y;   // 3584 warp tasks
    const int chHalf = wid & 1;
    const int strip  = wid >> 1;                       // 1792 strips
    const int cj = strip & 3;                          // 4 col chunks of 14
    const int s2 = strip >> 2;
    const int ti = s2 % NROWT;                         // 14 row quads
    const int b  = s2 / NROWT;

    const int oi0 = TILE_R * ti;
    const int oj0 = WCHUNK * cj;
    const int xr0 = 2*TILE_R*ti - 1;                   // first x row
    const int xc0 = 2*oj0 - 1;                         // first x col

    const float2 NEG  = make_float2(-FLT_MAX, -FLT_MAX);
    const float2 ZERO = make_float2(0.f, 0.f);
    const float wv0 = 0.125f, wv1 = 0.375f;            // (1,3,3,1)/8

    const bool okTop     = (ti != 0);
    const bool okBot     = (ti != NROWT - 1);
    const bool leftSkip  = (cj == 0);
    const bool rightSkip = (cj == 3);

    const float2* base = x + (size_t)b * 112 * 112 * 64 + chHalf * 32 + lane
                           + (long long)xr0 * ROWSTR;

    // Prime column xc0 -> cmPrev
    float2 cmPrev[NY];
    {
        float2 xv[NXROWS];
        LOADCOL(xv, xc0, !leftSkip);                   // xc0 < 0 only if cj==0
        MAKECM(cmPrev, xv);
    }

    float2 acc[TILE_R][2];                             // [row][col&1] ring
#pragma unroll
    for (int r = 0; r < TILE_R; r++) { acc[r][0] = ZERO; acc[r][1] = ZERO; }

    float2* ob = out + ((size_t)(b * 56 + oi0) * 56 + oj0) * 64
                     + chHalf * 32 + lane;

    // Double-buffered column pairs: buffer i&1 holds cols of iteration i.
    float2 xa[2][NXROWS], xb2[2][NXROWS];
    LOADCOL(xa[0],  xc0 + 1, true);
    LOADCOL(xb2[0], xc0 + 2, true);

#pragma unroll
    for (int i = 0; i < 15; i++) {
        const int cur = i & 1, nxt = cur ^ 1;
        if (i < 14) {                                  // 22-load burst, iter i+1
            const bool ok = (i < 13) || !rightSkip;    // only cols 112/113 bad
            LOADCOL(xa[nxt],  xc0 + 3 + 2*i, ok);
            LOADCOL(xb2[nxt], xc0 + 4 + 2*i, ok);
        }

        float2 cmA[NY];
        MAKECM(cmA, xa[cur]);
        STEP(cmPrev, cmA, 2*i);                        // y col ty = 2i

        float2 cmB[NY];
        MAKECM(cmB, xb2[cur]);
        STEP(cmA, cmB, 2*i + 1);                       // y col ty = 2i+1

        if (i >= 1) {                                  // out col i-1 complete
            const int wl = i - 1, slot = wl & 1;
#pragma unroll
            for (int rl = 0; rl < TILE_R; rl++) {
                ob[((size_t)rl * 56 + wl) * 64] = acc[rl][slot];
                acc[rl][slot] = ZERO;
            }
        }

#pragma unroll
        for (int k = 0; k < NY; k++) cmPrev[k] = cmB[k];
    }
}

extern "C" void kernel_launch(void* const* d_in, const int* in_sizes, int n_in,
                              void* d_out, int out_size) {
    const float2* x = (const float2*)d_in[0];   // (32,112,112,128) f32
    // d_in[1] = blur kernel, baked into (1,3,3,1)/8
    float2* out = (float2*)d_out;               // (32,56,56,128) f32

    // 32 b x 14 row-quads x 4 col chunks x 2 channel halves = 3584 warp tasks
    dim3 block(32, 4);
    dim3 grid(3584 / 4);                        // 896 blocks
    mbp_kernel<<<grid, block>>>(x, out);
}